// round 12
// baseline (speedup 1.0000x reference)
#include <cuda_runtime.h>
#include <cuda_fp16.h>
#include <cstdint>

// Problem constants
#define NT    48
#define NE    48
#define BATCH 32
#define VS    512
#define M_ROWS (NT * BATCH)   // 1536 rows per z

// ---------------------------------------------------------------------------
// Device-global scratch (no allocations allowed)
// ---------------------------------------------------------------------------
__device__ float g_A[M_ROWS * VS];            // ta + b1, [t*32+b][h]
__device__ float g_E[M_ROWS * VS];            // eb,      [n*32+b][h]

__device__ __forceinline__ uint32_t smem_u32(const void* p) {
    uint32_t a;
    asm("{ .reg .u64 t; cvta.to.shared.u64 t, %1; cvt.u32.u64 %0, t; }"
        : "=r"(a) : "l"(p));
    return a;
}

// ---------------------------------------------------------------------------
// Kernel 1: mma.sync fp16 GEMM; BOTH operands converted fp32->fp16 in the
// load path (no separate conversion kernel). fp32 output.
// C[m,h] = sum_v fp16(X[m,v]) * fp16(W1[h, z*VS+v])  (+ b1[h] for z==0)
// CTA tile 128m x 128h, 8 warps, warp tile 64x32 (m16n8k16.f16).
// K chunks of 64 (register prefetch rx/rw), double-buffered smem,
// 144B padded rows. grid = (4 h, 12 m, 2 z), 256 threads.
// ---------------------------------------------------------------------------
#define NCHUNK 8                   // 8 chunks of K=64
#define CK 64
#define ROW_B 144                  // 64 fp16 (128B) + 16B pad
#define TILE_B (128 * ROW_B)       // 18432 per tile
#define STAGE (2 * TILE_B)         // X + W = 36864
#define GEMM_SMEM (2 * STAGE)      // 73728

__device__ __forceinline__ void ldsm4(uint32_t* f, uint32_t addr) {
    asm volatile("ldmatrix.sync.aligned.m8n8.x4.shared.b16 {%0,%1,%2,%3}, [%4];"
                 : "=r"(f[0]), "=r"(f[1]), "=r"(f[2]), "=r"(f[3]) : "r"(addr));
}
#define MMA_F16(acc, a, b0, b1)                                               \
    asm volatile(                                                             \
        "mma.sync.aligned.m16n8k16.row.col.f32.f16.f16.f32 "                  \
        "{%0,%1,%2,%3}, {%4,%5,%6,%7}, {%8,%9}, {%0,%1,%2,%3};"               \
        : "+f"((acc)[0]), "+f"((acc)[1]), "+f"((acc)[2]), "+f"((acc)[3])      \
        : "r"((a)[0]), "r"((a)[1]), "r"((a)[2]), "r"((a)[3]),                 \
          "r"(b0), "r"(b1))

__global__ __launch_bounds__(256) void mma_gemm_kernel(
    const float* __restrict__ Tg, const float* __restrict__ Eg,
    const float* __restrict__ W1, const float* __restrict__ b1)
{
    extern __shared__ char smem[];
    const uint32_t sbase = smem_u32(smem);
    const int tid  = threadIdx.x;
    const int lane = tid & 31;
    const int warp = tid >> 5;            // 0..7
    const int z  = blockIdx.z;
    const int m0 = blockIdx.y * 128;
    const int h0 = blockIdx.x * 128;
    float* __restrict__ C = z ? g_E : g_A;
    const float* __restrict__ Xf = z ? Eg : Tg;   // fp32 X rows [m][v]
    const int woff = z * VS;                      // W1 column offset

    const int wm0 = (warp & 1) * 64;       // warp m offset: {0,64}
    const int wn0 = (warp >> 1) * 32;      // warp h offset: {0,32,64,96}
    const int lg  = lane >> 2;             // group id 0..7
    const int lq  = lane & 3;              // quad id 0..3

    // ldmatrix per-lane base offsets (within a tile)
    const int m4 = lane >> 3;
    const int r8 = lane & 7;
    const uint32_t aOff = (uint32_t)((wm0 + (m4 & 1) * 8 + r8) * ROW_B + (m4 >> 1) * 16);
    const uint32_t bOff = (uint32_t)((wn0 + (m4 >> 1) * 8 + r8) * ROW_B + (m4 & 1) * 16);

    float acc[4][4][4];
#pragma unroll
    for (int mi = 0; mi < 4; mi++)
#pragma unroll
        for (int ni = 0; ni < 4; ni++)
#pragma unroll
            for (int r = 0; r < 4; r++) acc[mi][ni][r] = 0.f;

    // Load mapping: 2048 float4 per operand per chunk; 8 per thread.
    const int xrow = tid >> 4;             // row (0..127 via i*16+)
    const int xc16 = tid & 15;             // float4 within 64-col row

    float4 rx[8], rw[8];                   // fp32 prefetch (next chunk)

    auto prefetch = [&](int c) {
        const int k0 = c * CK;
#pragma unroll
        for (int i = 0; i < 8; i++) {
            const int row = i * 16 + xrow;
            rx[i] = *(const float4*)(Xf + (size_t)(m0 + row) * VS + k0 + xc16 * 4);
            rw[i] = *(const float4*)(W1 + (size_t)(h0 + row) * (2 * VS) + woff + k0 + xc16 * 4);
        }
    };

    auto store = [&](int c) {
        char* bufX = smem + (c & 1) * STAGE;
        char* bufW = bufX + TILE_B;
#pragma unroll
        for (int i = 0; i < 8; i++) {
            const int row = i * 16 + xrow;
            const uint32_t d = (uint32_t)(row * ROW_B + xc16 * 8);
            __half2 x01 = __floats2half2_rn(rx[i].x, rx[i].y);
            __half2 x23 = __floats2half2_rn(rx[i].z, rx[i].w);
            uint2 xp; xp.x = *(uint32_t*)&x01; xp.y = *(uint32_t*)&x23;
            *(uint2*)(bufX + d) = xp;
            __half2 w01 = __floats2half2_rn(rw[i].x, rw[i].y);
            __half2 w23 = __floats2half2_rn(rw[i].z, rw[i].w);
            uint2 wp; wp.x = *(uint32_t*)&w01; wp.y = *(uint32_t*)&w23;
            *(uint2*)(bufW + d) = wp;
        }
    };

    auto compute = [&](int c) {
        const uint32_t s0 = sbase + (c & 1) * STAGE;
        const uint32_t sA = s0 + aOff;
        const uint32_t sB = s0 + TILE_B + bOff;
#pragma unroll
        for (int kc = 0; kc < 4; kc++) {
            uint32_t bf[2][4];
            ldsm4(bf[0], sB + kc * 32);
            ldsm4(bf[1], sB + 16 * ROW_B + kc * 32);
#pragma unroll
            for (int mi = 0; mi < 4; mi++) {
                uint32_t a[4];
                ldsm4(a, sA + mi * 16 * ROW_B + kc * 32);
#pragma unroll
                for (int ni = 0; ni < 4; ni++)
                    MMA_F16(acc[mi][ni], a,
                            bf[ni >> 1][(ni & 1) * 2], bf[ni >> 1][(ni & 1) * 2 + 1]);
            }
        }
    };

    // Prologue: chunk0 to smem, chunk1 in regs
    prefetch(0);
    store(0);
    prefetch(1);
    __syncthreads();

    for (int c = 0; c < NCHUNK; c++) {
        compute(c);
        __syncthreads();
        if (c + 1 < NCHUNK) {
            store(c + 1);                  // regs (chunk c+1) -> other buffer
            if (c + 2 < NCHUNK) prefetch(c + 2);   // hidden by next compute
            __syncthreads();
        }
    }

    // Epilogue: bias (z==0) + fp32 float2 stores
#pragma unroll
    for (int mi = 0; mi < 4; mi++) {
        const int m = m0 + wm0 + mi * 16 + lg;
#pragma unroll
        for (int ni = 0; ni < 4; ni++) {
            const int h = h0 + wn0 + ni * 8 + lq * 2;
            float2 bias = make_float2(0.f, 0.f);
            if (z == 0) bias = *(const float2*)(b1 + h);
            float2 v0 = make_float2(acc[mi][ni][0] + bias.x, acc[mi][ni][1] + bias.y);
            float2 v1 = make_float2(acc[mi][ni][2] + bias.x, acc[mi][ni][3] + bias.y);
            *(float2*)(C + (size_t)m * VS + h)       = v0;
            *(float2*)(C + (size_t)(m + 8) * VS + h) = v1;
        }
    }
}

// ---------------------------------------------------------------------------
// Kernel 2: out[t,n,b] = sum_h w2[h]*tanh(A[t,b,h]+E[n,b,h]) + b2
// fp32 pipeline (minimum xu-pipe ops: 1 MUFU per element, no CVTs).
// Block = (2 targets, b): 768 blocks for occupancy. 256 threads.
// ---------------------------------------------------------------------------
#define TPB 2

__device__ __forceinline__ float tanh_fast(float x) {
    float y;
    asm("tanh.approx.f32 %0, %1;" : "=f"(y) : "f"(x));
    return y;
}

__global__ __launch_bounds__(256) void fuse_kernel(
    const float* __restrict__ W2, const float* __restrict__ b2,
    float* __restrict__ out)
{
    const int bb = blockIdx.y;
    const int t0 = blockIdx.x * TPB;
    const int warp = threadIdx.x >> 5;
    const int lane = threadIdx.x & 31;

    const float4* W4 = (const float4*)W2;
    float4 w[4];
#pragma unroll
    for (int j = 0; j < 4; j++) w[j] = __ldg(&W4[lane + 32 * j]);

    float4 a[TPB][4];
#pragma unroll
    for (int t = 0; t < TPB; t++) {
        const float4* A4 = (const float4*)(g_A + ((size_t)((t0 + t) * BATCH + bb)) * VS);
#pragma unroll
        for (int j = 0; j < 4; j++) a[t][j] = A4[lane + 32 * j];
    }
    const float b2v = __ldg(b2);

    for (int n = warp; n < NE; n += 8) {
        const float4* E4 = (const float4*)(g_E + ((size_t)(n * BATCH + bb)) * VS);
        float s[TPB] = {0.f, 0.f};
#pragma unroll
        for (int j = 0; j < 4; j++) {
            float4 e = __ldg(&E4[lane + 32 * j]);
#pragma unroll
            for (int t = 0; t < TPB; t++) {
                s[t] = fmaf(w[j].x, tanh_fast(a[t][j].x + e.x), s[t]);
                s[t] = fmaf(w[j].y, tanh_fast(a[t][j].y + e.y), s[t]);
                s[t] = fmaf(w[j].z, tanh_fast(a[t][j].z + e.z), s[t]);
                s[t] = fmaf(w[j].w, tanh_fast(a[t][j].w + e.w), s[t]);
            }
        }
#pragma unroll
        for (int off = 16; off; off >>= 1)
#pragma unroll
            for (int t = 0; t < TPB; t++)
                s[t] += __shfl_xor_sync(0xffffffffu, s[t], off);
        if (lane == 0) {
#pragma unroll
            for (int t = 0; t < TPB; t++)
                out[((size_t)(t0 + t) * NE + n) * BATCH + bb] = s[t] + b2v;
        }
    }
}

// ---------------------------------------------------------------------------
// Launch: inputs in metadata order: targets, embeddings, W1, b1, W2, b2
// ---------------------------------------------------------------------------
extern "C" void kernel_launch(void* const* d_in, const int* in_sizes, int n_in,
                              void* d_out, int out_size)
{
    const float* targets    = (const float*)d_in[0];
    const float* embeddings = (const float*)d_in[1];
    const float* W1         = (const float*)d_in[2];
    const float* b1         = (const float*)d_in[3];
    const float* W2         = (const float*)d_in[4];
    const float* b2         = (const float*)d_in[5];
    float* out = (float*)d_out;

    cudaFuncSetAttribute(mma_gemm_kernel,
                         cudaFuncAttributeMaxDynamicSharedMemorySize, GEMM_SMEM);

    dim3 gg(4, 12, 2);   // h-tiles, m-tiles, z
    mma_gemm_kernel<<<gg, 256, GEMM_SMEM>>>(targets, embeddings, W1, b1);

    dim3 gf(NT / TPB, BATCH);   // 24 x 32 = 768 blocks
    fuse_kernel<<<gf, 256>>>(W2, b2, out);
}

// round 13
// speedup vs baseline: 1.0152x; 1.0152x over previous
#include <cuda_runtime.h>
#include <cuda_fp16.h>
#include <cstdint>

// Problem constants
#define NT    48
#define NE    48
#define BATCH 32
#define VS    512
#define M_ROWS (NT * BATCH)   // 1536 rows per z

// ---------------------------------------------------------------------------
// Device-global scratch (no allocations allowed)
// ---------------------------------------------------------------------------
__device__ float g_A[M_ROWS * VS];            // ta + b1, [t*32+b][h]
__device__ float g_E[M_ROWS * VS];            // eb,      [n*32+b][h]

__device__ __forceinline__ uint32_t smem_u32(const void* p) {
    uint32_t a;
    asm("{ .reg .u64 t; cvta.to.shared.u64 t, %1; cvt.u32.u64 %0, t; }"
        : "=r"(a) : "l"(p));
    return a;
}

// ---------------------------------------------------------------------------
// Kernel 1: mma.sync fp16 GEMM; BOTH operands converted fp32->fp16 in the
// load path (no separate conversion kernel). fp32 output.  (unchanged, r12)
// ---------------------------------------------------------------------------
#define NCHUNK 8                   // 8 chunks of K=64
#define CK 64
#define ROW_B 144                  // 64 fp16 (128B) + 16B pad
#define TILE_B (128 * ROW_B)       // 18432 per tile
#define STAGE (2 * TILE_B)         // X + W = 36864
#define GEMM_SMEM (2 * STAGE)      // 73728

__device__ __forceinline__ void ldsm4(uint32_t* f, uint32_t addr) {
    asm volatile("ldmatrix.sync.aligned.m8n8.x4.shared.b16 {%0,%1,%2,%3}, [%4];"
                 : "=r"(f[0]), "=r"(f[1]), "=r"(f[2]), "=r"(f[3]) : "r"(addr));
}
#define MMA_F16(acc, a, b0, b1)                                               \
    asm volatile(                                                             \
        "mma.sync.aligned.m16n8k16.row.col.f32.f16.f16.f32 "                  \
        "{%0,%1,%2,%3}, {%4,%5,%6,%7}, {%8,%9}, {%0,%1,%2,%3};"               \
        : "+f"((acc)[0]), "+f"((acc)[1]), "+f"((acc)[2]), "+f"((acc)[3])      \
        : "r"((a)[0]), "r"((a)[1]), "r"((a)[2]), "r"((a)[3]),                 \
          "r"(b0), "r"(b1))

__global__ __launch_bounds__(256) void mma_gemm_kernel(
    const float* __restrict__ Tg, const float* __restrict__ Eg,
    const float* __restrict__ W1, const float* __restrict__ b1)
{
    extern __shared__ char smem[];
    const uint32_t sbase = smem_u32(smem);
    const int tid  = threadIdx.x;
    const int lane = tid & 31;
    const int warp = tid >> 5;            // 0..7
    const int z  = blockIdx.z;
    const int m0 = blockIdx.y * 128;
    const int h0 = blockIdx.x * 128;
    float* __restrict__ C = z ? g_E : g_A;
    const float* __restrict__ Xf = z ? Eg : Tg;   // fp32 X rows [m][v]
    const int woff = z * VS;                      // W1 column offset

    const int wm0 = (warp & 1) * 64;       // warp m offset: {0,64}
    const int wn0 = (warp >> 1) * 32;      // warp h offset: {0,32,64,96}
    const int lg  = lane >> 2;             // group id 0..7
    const int lq  = lane & 3;              // quad id 0..3

    const int m4 = lane >> 3;
    const int r8 = lane & 7;
    const uint32_t aOff = (uint32_t)((wm0 + (m4 & 1) * 8 + r8) * ROW_B + (m4 >> 1) * 16);
    const uint32_t bOff = (uint32_t)((wn0 + (m4 >> 1) * 8 + r8) * ROW_B + (m4 & 1) * 16);

    float acc[4][4][4];
#pragma unroll
    for (int mi = 0; mi < 4; mi++)
#pragma unroll
        for (int ni = 0; ni < 4; ni++)
#pragma unroll
            for (int r = 0; r < 4; r++) acc[mi][ni][r] = 0.f;

    const int xrow = tid >> 4;             // row (0..127 via i*16+)
    const int xc16 = tid & 15;             // float4 within 64-col row

    float4 rx[8], rw[8];                   // fp32 prefetch (next chunk)

    auto prefetch = [&](int c) {
        const int k0 = c * CK;
#pragma unroll
        for (int i = 0; i < 8; i++) {
            const int row = i * 16 + xrow;
            rx[i] = *(const float4*)(Xf + (size_t)(m0 + row) * VS + k0 + xc16 * 4);
            rw[i] = *(const float4*)(W1 + (size_t)(h0 + row) * (2 * VS) + woff + k0 + xc16 * 4);
        }
    };

    auto store = [&](int c) {
        char* bufX = smem + (c & 1) * STAGE;
        char* bufW = bufX + TILE_B;
#pragma unroll
        for (int i = 0; i < 8; i++) {
            const int row = i * 16 + xrow;
            const uint32_t d = (uint32_t)(row * ROW_B + xc16 * 8);
            __half2 x01 = __floats2half2_rn(rx[i].x, rx[i].y);
            __half2 x23 = __floats2half2_rn(rx[i].z, rx[i].w);
            uint2 xp; xp.x = *(uint32_t*)&x01; xp.y = *(uint32_t*)&x23;
            *(uint2*)(bufX + d) = xp;
            __half2 w01 = __floats2half2_rn(rw[i].x, rw[i].y);
            __half2 w23 = __floats2half2_rn(rw[i].z, rw[i].w);
            uint2 wp; wp.x = *(uint32_t*)&w01; wp.y = *(uint32_t*)&w23;
            *(uint2*)(bufW + d) = wp;
        }
    };

    auto compute = [&](int c) {
        const uint32_t s0 = sbase + (c & 1) * STAGE;
        const uint32_t sA = s0 + aOff;
        const uint32_t sB = s0 + TILE_B + bOff;
#pragma unroll
        for (int kc = 0; kc < 4; kc++) {
            uint32_t bf[2][4];
            ldsm4(bf[0], sB + kc * 32);
            ldsm4(bf[1], sB + 16 * ROW_B + kc * 32);
#pragma unroll
            for (int mi = 0; mi < 4; mi++) {
                uint32_t a[4];
                ldsm4(a, sA + mi * 16 * ROW_B + kc * 32);
#pragma unroll
                for (int ni = 0; ni < 4; ni++)
                    MMA_F16(acc[mi][ni], a,
                            bf[ni >> 1][(ni & 1) * 2], bf[ni >> 1][(ni & 1) * 2 + 1]);
            }
        }
    };

    prefetch(0);
    store(0);
    prefetch(1);
    __syncthreads();

    for (int c = 0; c < NCHUNK; c++) {
        compute(c);
        __syncthreads();
        if (c + 1 < NCHUNK) {
            store(c + 1);
            if (c + 2 < NCHUNK) prefetch(c + 2);
            __syncthreads();
        }
    }

#pragma unroll
    for (int mi = 0; mi < 4; mi++) {
        const int m = m0 + wm0 + mi * 16 + lg;
#pragma unroll
        for (int ni = 0; ni < 4; ni++) {
            const int h = h0 + wn0 + ni * 8 + lq * 2;
            float2 bias = make_float2(0.f, 0.f);
            if (z == 0) bias = *(const float2*)(b1 + h);
            float2 v0 = make_float2(acc[mi][ni][0] + bias.x, acc[mi][ni][1] + bias.y);
            float2 v1 = make_float2(acc[mi][ni][2] + bias.x, acc[mi][ni][3] + bias.y);
            *(float2*)(C + (size_t)m * VS + h)       = v0;
            *(float2*)(C + (size_t)(m + 8) * VS + h) = v1;
        }
    }
}

// ---------------------------------------------------------------------------
// Kernel 2: out[t,n,b] = sum_h w2[h]*tanh(A[t,b,h]+E[n,b,h]) + b2
// A rows in SMEM (frees 32 regs -> higher occupancy), w2 in regs,
// E streamed with batched float4 loads. Two accumulators per target.
// Block = (2 targets, b), 768 blocks, 256 threads.
// ---------------------------------------------------------------------------
#define TPB 2

__device__ __forceinline__ float tanh_fast(float x) {
    float y;
    asm("tanh.approx.f32 %0, %1;" : "=f"(y) : "f"(x));
    return y;
}

__global__ __launch_bounds__(256) void fuse_kernel(
    const float* __restrict__ W2, const float* __restrict__ b2,
    float* __restrict__ out)
{
    __shared__ float4 sA[TPB * 128];     // 4KB: A rows for t0, t0+1

    const int bb = blockIdx.y;
    const int t0 = blockIdx.x * TPB;
    const int tid = threadIdx.x;
    const int warp = tid >> 5;
    const int lane = tid & 31;

    // Cooperative stage of A rows: 256 float4, one per thread
    {
        const int r = tid >> 7;          // 0..1
        const int c = tid & 127;
        sA[r * 128 + c] =
            ((const float4*)(g_A + ((size_t)((t0 + r) * BATCH + bb)) * VS))[c];
    }

    const float4* W4 = (const float4*)W2;
    float4 w[4];
#pragma unroll
    for (int j = 0; j < 4; j++) w[j] = __ldg(&W4[lane + 32 * j]);
    const float b2v = __ldg(b2);
    __syncthreads();

    for (int n = warp; n < NE; n += 8) {
        const float4* E4 = (const float4*)(g_E + ((size_t)(n * BATCH + bb)) * VS);
        float4 e[4];
#pragma unroll
        for (int j = 0; j < 4; j++) e[j] = __ldg(&E4[lane + 32 * j]);

        float s0[TPB], s1[TPB];
#pragma unroll
        for (int t = 0; t < TPB; t++) { s0[t] = 0.f; s1[t] = 0.f; }

#pragma unroll
        for (int t = 0; t < TPB; t++) {
#pragma unroll
            for (int j = 0; j < 4; j++) {
                float4 av = sA[t * 128 + lane + 32 * j];
                s0[t] = fmaf(w[j].x, tanh_fast(av.x + e[j].x), s0[t]);
                s1[t] = fmaf(w[j].y, tanh_fast(av.y + e[j].y), s1[t]);
                s0[t] = fmaf(w[j].z, tanh_fast(av.z + e[j].z), s0[t]);
                s1[t] = fmaf(w[j].w, tanh_fast(av.w + e[j].w), s1[t]);
            }
        }

        float s[TPB];
#pragma unroll
        for (int t = 0; t < TPB; t++) s[t] = s0[t] + s1[t];
#pragma unroll
        for (int off = 16; off; off >>= 1)
#pragma unroll
            for (int t = 0; t < TPB; t++)
                s[t] += __shfl_xor_sync(0xffffffffu, s[t], off);
        if (lane == 0) {
#pragma unroll
            for (int t = 0; t < TPB; t++)
                out[((size_t)(t0 + t) * NE + n) * BATCH + bb] = s[t] + b2v;
        }
    }
}

// ---------------------------------------------------------------------------
// Launch: inputs in metadata order: targets, embeddings, W1, b1, W2, b2
// ---------------------------------------------------------------------------
extern "C" void kernel_launch(void* const* d_in, const int* in_sizes, int n_in,
                              void* d_out, int out_size)
{
    const float* targets    = (const float*)d_in[0];
    const float* embeddings = (const float*)d_in[1];
    const float* W1         = (const float*)d_in[2];
    const float* b1         = (const float*)d_in[3];
    const float* W2         = (const float*)d_in[4];
    const float* b2         = (const float*)d_in[5];
    float* out = (float*)d_out;

    cudaFuncSetAttribute(mma_gemm_kernel,
                         cudaFuncAttributeMaxDynamicSharedMemorySize, GEMM_SMEM);

    dim3 gg(4, 12, 2);   // h-tiles, m-tiles, z
    mma_gemm_kernel<<<gg, 256, GEMM_SMEM>>>(targets, embeddings, W1, b1);

    dim3 gf(NT / TPB, BATCH);   // 24 x 32 = 768 blocks
    fuse_kernel<<<gf, 256>>>(W2, b2, out);
}

// round 14
// speedup vs baseline: 1.0252x; 1.0099x over previous
#include <cuda_runtime.h>
#include <cuda_fp16.h>
#include <cstdint>

// Problem constants
#define NT    48
#define NE    48
#define BATCH 32
#define VS    512
#define M_ROWS (NT * BATCH)   // 1536 rows per z

// ---------------------------------------------------------------------------
// Device-global scratch (no allocations allowed)
// ---------------------------------------------------------------------------
__device__ float g_A[M_ROWS * VS];            // ta + b1, [t*32+b][h]
__device__ float g_E[M_ROWS * VS];            // eb,      [n*32+b][h]

__device__ __forceinline__ uint32_t smem_u32(const void* p) {
    uint32_t a;
    asm("{ .reg .u64 t; cvta.to.shared.u64 t, %1; cvt.u32.u64 %0, t; }"
        : "=r"(a) : "l"(p));
    return a;
}

// ---------------------------------------------------------------------------
// Kernel 1: mma.sync fp16 GEMM; BOTH operands converted fp32->fp16 in the
// load path (no separate conversion kernel). fp32 output.  (unchanged)
// ---------------------------------------------------------------------------
#define NCHUNK 8                   // 8 chunks of K=64
#define CK 64
#define ROW_B 144                  // 64 fp16 (128B) + 16B pad
#define TILE_B (128 * ROW_B)       // 18432 per tile
#define STAGE (2 * TILE_B)         // X + W = 36864
#define GEMM_SMEM (2 * STAGE)      // 73728

__device__ __forceinline__ void ldsm4(uint32_t* f, uint32_t addr) {
    asm volatile("ldmatrix.sync.aligned.m8n8.x4.shared.b16 {%0,%1,%2,%3}, [%4];"
                 : "=r"(f[0]), "=r"(f[1]), "=r"(f[2]), "=r"(f[3]) : "r"(addr));
}
#define MMA_F16(acc, a, b0, b1)                                               \
    asm volatile(                                                             \
        "mma.sync.aligned.m16n8k16.row.col.f32.f16.f16.f32 "                  \
        "{%0,%1,%2,%3}, {%4,%5,%6,%7}, {%8,%9}, {%0,%1,%2,%3};"               \
        : "+f"((acc)[0]), "+f"((acc)[1]), "+f"((acc)[2]), "+f"((acc)[3])      \
        : "r"((a)[0]), "r"((a)[1]), "r"((a)[2]), "r"((a)[3]),                 \
          "r"(b0), "r"(b1))

__global__ __launch_bounds__(256) void mma_gemm_kernel(
    const float* __restrict__ Tg, const float* __restrict__ Eg,
    const float* __restrict__ W1, const float* __restrict__ b1)
{
    extern __shared__ char smem[];
    const uint32_t sbase = smem_u32(smem);
    const int tid  = threadIdx.x;
    const int lane = tid & 31;
    const int warp = tid >> 5;            // 0..7
    const int z  = blockIdx.z;
    const int m0 = blockIdx.y * 128;
    const int h0 = blockIdx.x * 128;
    float* __restrict__ C = z ? g_E : g_A;
    const float* __restrict__ Xf = z ? Eg : Tg;   // fp32 X rows [m][v]
    const int woff = z * VS;                      // W1 column offset

    const int wm0 = (warp & 1) * 64;       // warp m offset: {0,64}
    const int wn0 = (warp >> 1) * 32;      // warp h offset: {0,32,64,96}
    const int lg  = lane >> 2;             // group id 0..7
    const int lq  = lane & 3;              // quad id 0..3

    const int m4 = lane >> 3;
    const int r8 = lane & 7;
    const uint32_t aOff = (uint32_t)((wm0 + (m4 & 1) * 8 + r8) * ROW_B + (m4 >> 1) * 16);
    const uint32_t bOff = (uint32_t)((wn0 + (m4 >> 1) * 8 + r8) * ROW_B + (m4 & 1) * 16);

    float acc[4][4][4];
#pragma unroll
    for (int mi = 0; mi < 4; mi++)
#pragma unroll
        for (int ni = 0; ni < 4; ni++)
#pragma unroll
            for (int r = 0; r < 4; r++) acc[mi][ni][r] = 0.f;

    const int xrow = tid >> 4;             // row (0..127 via i*16+)
    const int xc16 = tid & 15;             // float4 within 64-col row

    float4 rx[8], rw[8];                   // fp32 prefetch (next chunk)

    auto prefetch = [&](int c) {
        const int k0 = c * CK;
#pragma unroll
        for (int i = 0; i < 8; i++) {
            const int row = i * 16 + xrow;
            rx[i] = *(const float4*)(Xf + (size_t)(m0 + row) * VS + k0 + xc16 * 4);
            rw[i] = *(const float4*)(W1 + (size_t)(h0 + row) * (2 * VS) + woff + k0 + xc16 * 4);
        }
    };

    auto store = [&](int c) {
        char* bufX = smem + (c & 1) * STAGE;
        char* bufW = bufX + TILE_B;
#pragma unroll
        for (int i = 0; i < 8; i++) {
            const int row = i * 16 + xrow;
            const uint32_t d = (uint32_t)(row * ROW_B + xc16 * 8);
            __half2 x01 = __floats2half2_rn(rx[i].x, rx[i].y);
            __half2 x23 = __floats2half2_rn(rx[i].z, rx[i].w);
            uint2 xp; xp.x = *(uint32_t*)&x01; xp.y = *(uint32_t*)&x23;
            *(uint2*)(bufX + d) = xp;
            __half2 w01 = __floats2half2_rn(rw[i].x, rw[i].y);
            __half2 w23 = __floats2half2_rn(rw[i].z, rw[i].w);
            uint2 wp; wp.x = *(uint32_t*)&w01; wp.y = *(uint32_t*)&w23;
            *(uint2*)(bufW + d) = wp;
        }
    };

    auto compute = [&](int c) {
        const uint32_t s0 = sbase + (c & 1) * STAGE;
        const uint32_t sA = s0 + aOff;
        const uint32_t sB = s0 + TILE_B + bOff;
#pragma unroll
        for (int kc = 0; kc < 4; kc++) {
            uint32_t bf[2][4];
            ldsm4(bf[0], sB + kc * 32);
            ldsm4(bf[1], sB + 16 * ROW_B + kc * 32);
#pragma unroll
            for (int mi = 0; mi < 4; mi++) {
                uint32_t a[4];
                ldsm4(a, sA + mi * 16 * ROW_B + kc * 32);
#pragma unroll
                for (int ni = 0; ni < 4; ni++)
                    MMA_F16(acc[mi][ni], a,
                            bf[ni >> 1][(ni & 1) * 2], bf[ni >> 1][(ni & 1) * 2 + 1]);
            }
        }
    };

    prefetch(0);
    store(0);
    prefetch(1);
    __syncthreads();

    for (int c = 0; c < NCHUNK; c++) {
        compute(c);
        __syncthreads();
        if (c + 1 < NCHUNK) {
            store(c + 1);
            if (c + 2 < NCHUNK) prefetch(c + 2);
            __syncthreads();
        }
    }

#pragma unroll
    for (int mi = 0; mi < 4; mi++) {
        const int m = m0 + wm0 + mi * 16 + lg;
#pragma unroll
        for (int ni = 0; ni < 4; ni++) {
            const int h = h0 + wn0 + ni * 8 + lq * 2;
            float2 bias = make_float2(0.f, 0.f);
            if (z == 0) bias = *(const float2*)(b1 + h);
            float2 v0 = make_float2(acc[mi][ni][0] + bias.x, acc[mi][ni][1] + bias.y);
            float2 v1 = make_float2(acc[mi][ni][2] + bias.x, acc[mi][ni][3] + bias.y);
            *(float2*)(C + (size_t)m * VS + h)       = v0;
            *(float2*)(C + (size_t)(m + 8) * VS + h) = v1;
        }
    }
}

// ---------------------------------------------------------------------------
// Kernel 2: out[t,n,b] = sum_h w2[h]*tanh(A[t,b,h]+E[n,b,h]) + b2
// A rows in SMEM, w2 in regs, E loads SOFTWARE-PIPELINED across the n-loop
// (prefetch n+8 while computing n) to keep the MUFU pipe fed.
// Block = (2 targets, b), 768 blocks, 256 threads.
// ---------------------------------------------------------------------------
#define TPB 2
#define NITER (NE / 8)   // 6

__device__ __forceinline__ float tanh_fast(float x) {
    float y;
    asm("tanh.approx.f32 %0, %1;" : "=f"(y) : "f"(x));
    return y;
}

__global__ __launch_bounds__(256) void fuse_kernel(
    const float* __restrict__ W2, const float* __restrict__ b2,
    float* __restrict__ out)
{
    __shared__ float4 sA[TPB * 128];     // 4KB: A rows for t0, t0+1

    const int bb = blockIdx.y;
    const int t0 = blockIdx.x * TPB;
    const int tid = threadIdx.x;
    const int warp = tid >> 5;
    const int lane = tid & 31;

    // Cooperative stage of A rows: 256 float4, one per thread
    {
        const int r = tid >> 7;          // 0..1
        const int c = tid & 127;
        sA[r * 128 + c] =
            ((const float4*)(g_A + ((size_t)((t0 + r) * BATCH + bb)) * VS))[c];
    }

    const float4* W4 = (const float4*)W2;
    float4 w[4];
#pragma unroll
    for (int j = 0; j < 4; j++) w[j] = __ldg(&W4[lane + 32 * j]);
    const float b2v = __ldg(b2);
    __syncthreads();

    // Prime the E pipeline for n = warp
    float4 e[4];
    {
        const float4* E4 = (const float4*)(g_E + ((size_t)(warp * BATCH + bb)) * VS);
#pragma unroll
        for (int j = 0; j < 4; j++) e[j] = __ldg(&E4[lane + 32 * j]);
    }

#pragma unroll
    for (int i = 0; i < NITER; i++) {
        const int n = warp + 8 * i;

        // Prefetch next n's E while this iteration computes
        float4 en[4];
        if (i + 1 < NITER) {
            const float4* E4n =
                (const float4*)(g_E + ((size_t)((n + 8) * BATCH + bb)) * VS);
#pragma unroll
            for (int j = 0; j < 4; j++) en[j] = __ldg(&E4n[lane + 32 * j]);
        }

        float s0[TPB], s1[TPB];
#pragma unroll
        for (int t = 0; t < TPB; t++) { s0[t] = 0.f; s1[t] = 0.f; }

#pragma unroll
        for (int t = 0; t < TPB; t++) {
#pragma unroll
            for (int j = 0; j < 4; j++) {
                float4 av = sA[t * 128 + lane + 32 * j];
                s0[t] = fmaf(w[j].x, tanh_fast(av.x + e[j].x), s0[t]);
                s1[t] = fmaf(w[j].y, tanh_fast(av.y + e[j].y), s1[t]);
                s0[t] = fmaf(w[j].z, tanh_fast(av.z + e[j].z), s0[t]);
                s1[t] = fmaf(w[j].w, tanh_fast(av.w + e[j].w), s1[t]);
            }
        }

        float s[TPB];
#pragma unroll
        for (int t = 0; t < TPB; t++) s[t] = s0[t] + s1[t];
#pragma unroll
        for (int off = 16; off; off >>= 1)
#pragma unroll
            for (int t = 0; t < TPB; t++)
                s[t] += __shfl_xor_sync(0xffffffffu, s[t], off);
        if (lane == 0) {
#pragma unroll
            for (int t = 0; t < TPB; t++)
                out[((size_t)(t0 + t) * NE + n) * BATCH + bb] = s[t] + b2v;
        }

#pragma unroll
        for (int j = 0; j < 4; j++) e[j] = en[j];
    }
}

// ---------------------------------------------------------------------------
// Launch: inputs in metadata order: targets, embeddings, W1, b1, W2, b2
// ---------------------------------------------------------------------------
extern "C" void kernel_launch(void* const* d_in, const int* in_sizes, int n_in,
                              void* d_out, int out_size)
{
    const float* targets    = (const float*)d_in[0];
    const float* embeddings = (const float*)d_in[1];
    const float* W1         = (const float*)d_in[2];
    const float* b1         = (const float*)d_in[3];
    const float* W2         = (const float*)d_in[4];
    const float* b2         = (const float*)d_in[5];
    float* out = (float*)d_out;

    cudaFuncSetAttribute(mma_gemm_kernel,
                         cudaFuncAttributeMaxDynamicSharedMemorySize, GEMM_SMEM);

    dim3 gg(4, 12, 2);   // h-tiles, m-tiles, z
    mma_gemm_kernel<<<gg, 256, GEMM_SMEM>>>(targets, embeddings, W1, b1);

    dim3 gf(NT / TPB, BATCH);   // 24 x 32 = 768 blocks
    fuse_kernel<<<gf, 256>>>(W2, b2, out);
}